// round 13
// baseline (speedup 1.0000x reference)
#include <cuda_runtime.h>
#include <cuda_bf16.h>
#include <math.h>

// NetVLAD: N=32, D=512, S=1600, K=64.
// d_in[0]=x [N,D,S] f32, d_in[1]=W [K,D] f32, d_in[2]=centroids [K,D] f32
// out: [N, K*D] f32

#define NN 32
#define DDIM 512
#define SDIM 1600
#define KK 64
#define NTILES 25   // s-tiles of 64 (k_logits / k_prep)

typedef __nv_bfloat16 bh;

__device__ __align__(16) bh g_xb[NN * DDIM * SDIM + 512]; // x bf16 (+pad for tail overshoot)
__device__ __align__(16) bh g_wb[KK * DDIM];              // W bf16
__device__ __align__(16) float g_invn[NN * SDIM];         // 1/||x(:,s)||
__device__ __align__(16) bh g_a[NN * KK * SDIM + 512];    // a' = softmax*invn (+pad)
__device__ __align__(16) float g_agg4[4][NN * KK * DDIM]; // agg, 4 s-quarters
__device__ __align__(16) float g_asum_part[NN * NTILES * KK];

__device__ __forceinline__ unsigned packbf(float lo, float hi) {
    __nv_bfloat162 h = __floats2bfloat162_rn(lo, hi);
    return *(unsigned*)&h;
}

__device__ __forceinline__ void mma_bf16(float* c, unsigned a0, unsigned a1,
                                         unsigned a2, unsigned a3,
                                         unsigned b0, unsigned b1) {
    asm volatile(
        "mma.sync.aligned.m16n8k16.row.col.f32.bf16.bf16.f32 "
        "{%0,%1,%2,%3},{%4,%5,%6,%7},{%8,%9},{%0,%1,%2,%3};\n"
        : "+f"(c[0]), "+f"(c[1]), "+f"(c[2]), "+f"(c[3])
        : "r"(a0), "r"(a1), "r"(a2), "r"(a3), "r"(b0), "r"(b1));
}

__device__ __forceinline__ void cpa16(unsigned dst, const void* src) {
    asm volatile("cp.async.ca.shared.global [%0], [%1], 16;\n"
                 :: "r"(dst), "l"(src));
}
// zero-fill variant: copies sz bytes (0 or 16), zero-fills the rest of 16.
__device__ __forceinline__ void cpa16z(unsigned dst, const void* src, int sz) {
    asm volatile("cp.async.ca.shared.global [%0], [%1], 16, %2;\n"
                 :: "r"(dst), "l"(src), "r"(sz));
}
__device__ __forceinline__ void cp_commit() {
    asm volatile("cp.async.commit_group;\n");
}
template <int N> __device__ __forceinline__ void cp_wait() {
    asm volatile("cp.async.wait_group %0;\n" :: "n"(N));
}
__device__ __forceinline__ void ldsm4(unsigned& r0, unsigned& r1, unsigned& r2,
                                      unsigned& r3, unsigned a) {
    asm volatile("ldmatrix.sync.aligned.m8n8.x4.shared.b16 {%0,%1,%2,%3},[%4];\n"
                 : "=r"(r0), "=r"(r1), "=r"(r2), "=r"(r3) : "r"(a));
}
__device__ __forceinline__ void ldsm4t(unsigned& r0, unsigned& r1, unsigned& r2,
                                       unsigned& r3, unsigned a) {
    asm volatile("ldmatrix.sync.aligned.m8n8.x4.trans.shared.b16 {%0,%1,%2,%3},[%4];\n"
                 : "=r"(r0), "=r"(r1), "=r"(r2), "=r"(r3) : "r"(a));
}

// ---------------------------------------------------------------------------
// k_prepw: W -> bf16.
// ---------------------------------------------------------------------------
__global__ __launch_bounds__(256) void k_prepw(const float* __restrict__ W) {
    int i = blockIdx.x * 256 + threadIdx.x;
    g_wb[i] = __float2bfloat16(W[i]);
}

// ---------------------------------------------------------------------------
// k_prep: x -> bf16 + per-pixel invn.
// grid (25, 32), 256 thr; thread t: pixel s = t&63, d-lane dq = t>>6.
// ---------------------------------------------------------------------------
__global__ __launch_bounds__(256) void k_prep(const float* __restrict__ x) {
    const int n = blockIdx.y;
    const int s0 = blockIdx.x * 64;
    const int tid = threadIdx.x;
    const int s = tid & 63, dq = tid >> 6;

    __shared__ float ssq[256];

    const float* xb = x + (size_t)n * DDIM * SDIM + s0 + s;
    bh* ob = g_xb + (size_t)n * DDIM * SDIM + s0 + s;

    float acc = 0.f;
#pragma unroll 8
    for (int dg = 0; dg < 128; dg++) {
        int d = dg * 4 + dq;
        float v = xb[(size_t)d * SDIM];
        acc += v * v;
        ob[(size_t)d * SDIM] = __float2bfloat16(v);
    }
    ssq[tid] = acc;
    __syncthreads();
    if (tid < 64) {
        float t = ssq[tid] + ssq[tid + 64] + ssq[tid + 128] + ssq[tid + 192];
        g_invn[n * SDIM + s0 + tid] = 1.f / fmaxf(sqrtf(t), 1e-12f);
    }
}

// ---------------------------------------------------------------------------
// k_logits: logits = W_bf[64,512] @ x_bf[512, 64 s], cp.async 3-stage ring +
// ldmatrix; 128 thr = 4 warps; warp w: k-rows [(w>>1)*32,+32), s-cols
// [(w&1)*32,+32) -> each operand read only 2x from smem.
// smem: W stages [64][80B] @ st*5120; X stages [32][144B] @ 15360+st*4608.
// ---------------------------------------------------------------------------
__global__ __launch_bounds__(128) void k_logits() {
    const int n = blockIdx.y;
    const int s0 = blockIdx.x * 64;
    const int tid = threadIdx.x;
    const int warp = tid >> 5, lane = tid & 31;
    const int gid = lane >> 2, tig = lane & 3;
    const int k0 = (warp >> 1) * 32;
    const int sh = (warp & 1) * 32;

    __shared__ __align__(16) char sm[29184];
    const unsigned smb = (unsigned)__cvta_generic_to_shared(sm);

    const bh* Wg = g_wb;
    const bh* Xg = g_xb + (size_t)n * DDIM * SDIM + s0;
    // staging: W 64 rows x 64B (2 thr/row), X 32 rows x 128B (4 thr/row)
    const int wr = tid >> 1, wb = (tid & 1) * 32, we = (tid & 1) * 16;
    const int xr = tid >> 2, xb2 = (tid & 3) * 32, xe = (tid & 3) * 16;

#define LSTAGE(c) do {                                                        \
        int _st = (c) % 3; int _dc = (c) * 32;                                \
        cpa16(smb + _st * 5120 + wr * 80 + wb,      Wg + wr * DDIM + _dc + we);     \
        cpa16(smb + _st * 5120 + wr * 80 + wb + 16, Wg + wr * DDIM + _dc + we + 8); \
        cpa16(smb + 15360 + _st * 4608 + xr * 144 + xb2,                      \
              Xg + (size_t)(_dc + xr) * SDIM + xe);                           \
        cpa16(smb + 15360 + _st * 4608 + xr * 144 + xb2 + 16,                 \
              Xg + (size_t)(_dc + xr) * SDIM + xe + 8);                       \
        cp_commit(); } while (0)

    float acc[2][4][4];
#pragma unroll
    for (int i = 0; i < 2; i++)
#pragma unroll
        for (int j = 0; j < 4; j++)
#pragma unroll
            for (int e = 0; e < 4; e++) acc[i][j][e] = 0.f;

    LSTAGE(0);
    LSTAGE(1);

    const int q = lane >> 3, rr = lane & 7;
    const int offA = (k0 + (q & 1) * 8 + rr) * 80 + (q >> 1) * 16;  // +1280 for i=1
    const int offB = ((q & 1) * 8 + rr) * 144 + (q >> 1) * 16;

    for (int c = 0; c < 16; c++) {
        if (c < 15) cp_wait<1>(); else cp_wait<0>();
        __syncthreads();
        const unsigned Wb = smb + (c % 3) * 5120;
        const unsigned Xb = smb + 15360 + (c % 3) * 4608;
#pragma unroll
        for (int kk2 = 0; kk2 < 16; kk2 += 8) {       // d-offset = 2*kk2
            unsigned p0, p1, p2, p3, u0, u1, u2, u3;
            ldsm4(p0, p1, p2, p3, Wb + offA + kk2 * 4);          // m-frag i=0
            ldsm4(u0, u1, u2, u3, Wb + offA + 1280 + kk2 * 4);   // m-frag i=1
#pragma unroll
            for (int np = 0; np < 2; np++) {
                unsigned b0, b1, b2, b3;
                ldsm4t(b0, b1, b2, b3,
                       Xb + offB + (kk2 * 2) * 144 + (sh + np * 16) * 2);
                mma_bf16(acc[0][np * 2],     p0, p1, p2, p3, b0, b1);
                mma_bf16(acc[0][np * 2 + 1], p0, p1, p2, p3, b2, b3);
                mma_bf16(acc[1][np * 2],     u0, u1, u2, u3, b0, b1);
                mma_bf16(acc[1][np * 2 + 1], u0, u1, u2, u3, b2, b3);
            }
        }
        if (c + 2 < 16) LSTAGE(c + 2);
        else cp_commit();
    }
    __syncthreads();
#undef LSTAGE

    // ---- epilogue (aliases stage buffers) ----
    float (*Lsh)[65] = (float(*)[65])sm;            // 16640
    float* red1   = (float*)(sm + 16640);           // 512 (2x64)
    float* red2   = (float*)(sm + 17664);           // 512
    float* sscale = (float*)(sm + 18688);           // 256
    float* sinv   = (float*)(sm + 18944);           // 256

#pragma unroll
    for (int i = 0; i < 2; i++)
#pragma unroll
        for (int j = 0; j < 4; j++) {
            Lsh[k0 + 16 * i + gid][sh + j * 8 + 2 * tig]         = acc[i][j][0];
            Lsh[k0 + 16 * i + gid][sh + j * 8 + 2 * tig + 1]     = acc[i][j][1];
            Lsh[k0 + 16 * i + gid + 8][sh + j * 8 + 2 * tig]     = acc[i][j][2];
            Lsh[k0 + 16 * i + gid + 8][sh + j * 8 + 2 * tig + 1] = acc[i][j][3];
        }
    if (tid < 64) sscale[tid] = g_invn[n * SDIM + s0 + tid];
    __syncthreads();

    // softmax: 2 threads per pixel (qq = k-half), s = pixel
    const int qq = tid >> 6, s = tid & 63;
    const float sc = sscale[s];

    float m = -1e30f;
#pragma unroll
    for (int kq = 0; kq < 32; kq++) m = fmaxf(m, Lsh[qq * 32 + kq][s] * sc);
    red1[qq * 64 + s] = m;
    __syncthreads();
    m = fmaxf(red1[s], red1[64 + s]);

    float sump = 0.f;
#pragma unroll
    for (int kq = 0; kq < 32; kq++) {
        float e = __expf(Lsh[qq * 32 + kq][s] * sc - m);
        Lsh[qq * 32 + kq][s] = e;
        sump += e;
    }
    red2[qq * 64 + s] = sump;
    __syncthreads();
    if (qq == 0) sinv[s] = 1.f / (red2[s] + red2[64 + s]);
    __syncthreads();

    // a_sum partial: 2 threads per k, each sums 32 pixels
    {
        const int k = tid & 63;
        float t = 0.f;
#pragma unroll
        for (int sq = 0; sq < 32; sq++) {
            int sp = qq * 32 + sq;
            t += Lsh[k][sp] * sinv[sp];
        }
        red1[qq * 64 + k] = t;
    }
    __syncthreads();
    if (tid < 64)
        g_asum_part[((size_t)n * NTILES + blockIdx.x) * KK + tid] =
            red1[tid] + red1[64 + tid];

    // a' = softmax * invn -> bf16 pairs
    unsigned* ab32 = (unsigned*)g_a + (size_t)n * KK * (SDIM / 2) + (s0 >> 1);
#pragma unroll
    for (int i = 0; i < 16; i++) {
        int idx = tid + i * 128;
        int k = idx >> 5, s2 = (idx & 31) * 2;
        float v0 = Lsh[k][s2] * sinv[s2] * sscale[s2];
        float v1 = Lsh[k][s2 + 1] * sinv[s2 + 1] * sscale[s2 + 1];
        ab32[(size_t)k * (SDIM / 2) + (s2 >> 1)] = packbf(v0, v1);
    }
}

// ---------------------------------------------------------------------------
// k_agg: agg[d,k] += sum_s x_bf[d,s]*a'[k,s]; 128 thr = 4 warps; warp w:
// d-rows [(w>>1)*32,+32), k-cols [(w&1)*32,+32).
// grid (8 d-tiles, 32 n, 4 s-quarters); 400 s = 13 chunks of 32, tail s
// zero-filled on the a' operand (x * 0 = 0, no special tail path).
// smem: X stages [64][80B] @ st*5120; A stages [64][80B] @ 15360+st*5120.
// ---------------------------------------------------------------------------
__global__ __launch_bounds__(128) void k_agg() {
    const int n = blockIdx.y;
    const int d0 = blockIdx.x * 64;
    const int h = blockIdx.z;          // s-quarter
    const int tid = threadIdx.x;
    const int warp = tid >> 5, lane = tid & 31;
    const int gid = lane >> 2, tig = lane & 3;
    const int dw0 = (warp >> 1) * 32;
    const int kh = (warp & 1) * 32;

    __shared__ __align__(16) char sm[30720];
    const unsigned smb = (unsigned)__cvta_generic_to_shared(sm);

    const bh* Xg = g_xb + ((size_t)n * DDIM + d0) * SDIM;
    const bh* Ag = g_a + (size_t)n * KK * SDIM;
    const int rt = tid >> 2, ab2 = (tid & 3) * 16, ae = (tid & 3) * 8;
    const int sbase = h * 400;

#define ASTAGE(c) do {                                                        \
        int _st = (c) % 3; int _sc = sbase + (c) * 32;                        \
        int _sz = ((c) * 32 + ae < 400) ? 16 : 0;                             \
        cpa16(smb + _st * 5120 + rt * 80 + ab2,                               \
              Xg + (size_t)rt * SDIM + _sc + ae);                             \
        cpa16(smb + _st * 5120 + (rt + 32) * 80 + ab2,                        \
              Xg + (size_t)(rt + 32) * SDIM + _sc + ae);                      \
        cpa16z(smb + 15360 + _st * 5120 + rt * 80 + ab2,                      \
               Ag + (size_t)rt * SDIM + _sc + ae, _sz);                       \
        cpa16z(smb + 15360 + _st * 5120 + (rt + 32) * 80 + ab2,               \
               Ag + (size_t)(rt + 32) * SDIM + _sc + ae, _sz);                \
        cp_commit(); } while (0)

    float acc[2][4][4];
#pragma unroll
    for (int i = 0; i < 2; i++)
#pragma unroll
        for (int j = 0; j < 4; j++)
#pragma unroll
            for (int e = 0; e < 4; e++) acc[i][j][e] = 0.f;

    ASTAGE(0);
    ASTAGE(1);

    const int q = lane >> 3, rr = lane & 7;
    const int offA = (dw0 + (q & 1) * 8 + rr) * 80 + (q >> 1) * 16;  // +1280 i=1
    const int offB = (kh + q * 8 + rr) * 80;

    for (int c = 0; c < 13; c++) {
        if (c < 12) cp_wait<1>(); else cp_wait<0>();
        __syncthreads();
        const unsigned Xb = smb + (c % 3) * 5120;
        const unsigned Ab = smb + 15360 + (c % 3) * 5120;
#pragma unroll
        for (int kk2 = 0; kk2 < 16; kk2 += 8) {       // s-offset = 2*kk2
            unsigned x0, x1, x2, x3, y0, y1, y2, y3;
            ldsm4(x0, x1, x2, x3, Xb + offA + kk2 * 4);           // i=0
            ldsm4(y0, y1, y2, y3, Xb + offA + 1280 + kk2 * 4);    // i=1
            unsigned p0, p1, p2, p3, q0, q1, q2, q3;
            ldsm4(p0, p1, p2, p3, Ab + offB + kk2 * 4);        // b0 of j=0..3
            ldsm4(q0, q1, q2, q3, Ab + offB + kk2 * 4 + 16);   // b1 of j=0..3
            mma_bf16(acc[0][0], x0, x1, x2, x3, p0, q0);
            mma_bf16(acc[0][1], x0, x1, x2, x3, p1, q1);
            mma_bf16(acc[0][2], x0, x1, x2, x3, p2, q2);
            mma_bf16(acc[0][3], x0, x1, x2, x3, p3, q3);
            mma_bf16(acc[1][0], y0, y1, y2, y3, p0, q0);
            mma_bf16(acc[1][1], y0, y1, y2, y3, p1, q1);
            mma_bf16(acc[1][2], y0, y1, y2, y3, p2, q2);
            mma_bf16(acc[1][3], y0, y1, y2, y3, p3, q3);
        }
        if (c + 2 < 13) ASTAGE(c + 2);
        else cp_commit();
    }
    __syncthreads();
#undef ASTAGE

    // transpose: C[d = dw0+16i+gid(+8)][k = kh+8j+2tig(+1)] -> Tsh[k][d]
    float (*Tsh)[68] = (float(*)[68])sm;   // 17408, aliases stages
#pragma unroll
    for (int i = 0; i < 2; i++)
#pragma unroll
        for (int j = 0; j < 4; j++) {
            Tsh[kh + j * 8 + 2 * tig][dw0 + 16 * i + gid]         = acc[i][j][0];
            Tsh[kh + j * 8 + 2 * tig + 1][dw0 + 16 * i + gid]     = acc[i][j][1];
            Tsh[kh + j * 8 + 2 * tig][dw0 + 16 * i + gid + 8]     = acc[i][j][2];
            Tsh[kh + j * 8 + 2 * tig + 1][dw0 + 16 * i + gid + 8] = acc[i][j][3];
        }
    __syncthreads();
    float* dst = &g_agg4[h][(size_t)n * KK * DDIM + d0];
#pragma unroll
    for (int i = 0; i < 8; i++) {
        int idx = tid + i * 128;
        int k = idx >> 4, dd4 = (idx & 15) * 4;
        *(float4*)&dst[(size_t)k * DDIM + dd4] = *(const float4*)&Tsh[k][dd4];
    }
}

// ---------------------------------------------------------------------------
// k_final: a_sum reduce; vlad = sum(agg quarters) - a_sum*c; intra-norm; *1/8.
// grid (64,32), 128 thr.
// ---------------------------------------------------------------------------
__global__ __launch_bounds__(128) void k_final(const float* __restrict__ cent,
                                               float* __restrict__ out) {
    const int k = blockIdx.x, n = blockIdx.y;
    const int tid = threadIdx.x;

    __shared__ float s_as;
    __shared__ float wpart[4];

    if (tid < 32) {
        float p = (tid < NTILES)
                      ? g_asum_part[((size_t)n * NTILES + tid) * KK + k]
                      : 0.f;
#pragma unroll
        for (int o = 16; o > 0; o >>= 1) p += __shfl_xor_sync(0xffffffffu, p, o);
        if (tid == 0) s_as = p;
    }
    __syncthreads();
    const float as = s_as;

    const size_t base = ((size_t)n * KK + k) * DDIM + tid * 4;
    float4 a0 = *(const float4*)&g_agg4[0][base];
    float4 a1 = *(const float4*)&g_agg4[1][base];
    float4 a2 = *(const float4*)&g_agg4[2][base];
    float4 a3 = *(const float4*)&g_agg4[3][base];
    float4 c4 = *(const float4*)&cent[(size_t)k * DDIM + tid * 4];
    float vx = (a0.x + a1.x) + (a2.x + a3.x) - as * c4.x;
    float vy = (a0.y + a1.y) + (a2.y + a3.y) - as * c4.y;
    float vz = (a0.z + a1.z) + (a2.z + a3.z) - as * c4.z;
    float vw = (a0.w + a1.w) + (a2.w + a3.w) - as * c4.w;
    float ss = vx * vx + vy * vy + vz * vz + vw * vw;

#pragma unroll
    for (int o = 16; o > 0; o >>= 1) ss += __shfl_xor_sync(0xffffffffu, ss, o);
    if ((tid & 31) == 0) wpart[tid >> 5] = ss;
    __syncthreads();
    float tot = wpart[0] + wpart[1] + wpart[2] + wpart[3];

    const float inv = 0.125f / fmaxf(sqrtf(tot), 1e-12f);
    float4 o4 = make_float4(vx * inv, vy * inv, vz * inv, vw * inv);
    *(float4*)&out[(size_t)n * (KK * DDIM) + (size_t)k * DDIM + tid * 4] = o4;
}

extern "C" void kernel_launch(void* const* d_in, const int* in_sizes, int n_in,
                              void* d_out, int out_size) {
    const float* x    = (const float*)d_in[0];
    const float* W    = (const float*)d_in[1];
    const float* cent = (const float*)d_in[2];
    float* out = (float*)d_out;

    k_prepw<<<128, 256>>>(W);
    k_prep<<<dim3(NTILES, NN), 256>>>(x);
    k_logits<<<dim3(NTILES, NN), 128>>>();
    k_agg<<<dim3(8, NN, 4), 128>>>();
    k_final<<<dim3(KK, NN), 128>>>(cent, out);
}

// round 14
// speedup vs baseline: 1.2593x; 1.2593x over previous
#include <cuda_runtime.h>
#include <cuda_bf16.h>
#include <math.h>

// NetVLAD: N=32, D=512, S=1600, K=64.
// d_in[0]=x [N,D,S] f32, d_in[1]=W [K,D] f32, d_in[2]=centroids [K,D] f32
// out: [N, K*D] f32

#define NN 32
#define DDIM 512
#define SDIM 1600
#define KK 64
#define NTILES 25   // s-tiles of 64

typedef __nv_bfloat16 bh;

__device__ __align__(16) bh g_xb[NN * DDIM * SDIM];       // x bf16 (written by k_logits)
__device__ __align__(16) bh g_wb[KK * DDIM];              // W bf16
__device__ __align__(16) bh g_a[NN * KK * SDIM];          // a' = softmax*invn
__device__ __align__(16) float g_agg2[2][NN * KK * DDIM]; // agg, 2 s-halves
__device__ __align__(16) float g_asum_part[NN * NTILES * KK];

__device__ __forceinline__ unsigned packbf(float lo, float hi) {
    __nv_bfloat162 h = __floats2bfloat162_rn(lo, hi);
    return *(unsigned*)&h;
}

__device__ __forceinline__ void mma_bf16(float* c, unsigned a0, unsigned a1,
                                         unsigned a2, unsigned a3,
                                         unsigned b0, unsigned b1) {
    asm volatile(
        "mma.sync.aligned.m16n8k16.row.col.f32.bf16.bf16.f32 "
        "{%0,%1,%2,%3},{%4,%5,%6,%7},{%8,%9},{%0,%1,%2,%3};\n"
        : "+f"(c[0]), "+f"(c[1]), "+f"(c[2]), "+f"(c[3])
        : "r"(a0), "r"(a1), "r"(a2), "r"(a3), "r"(b0), "r"(b1));
}

__device__ __forceinline__ void cpa16(unsigned dst, const void* src) {
    asm volatile("cp.async.ca.shared.global [%0], [%1], 16;\n"
                 :: "r"(dst), "l"(src));
}
__device__ __forceinline__ void cp_commit() {
    asm volatile("cp.async.commit_group;\n");
}
template <int N> __device__ __forceinline__ void cp_wait() {
    asm volatile("cp.async.wait_group %0;\n" :: "n"(N));
}
__device__ __forceinline__ void ldsm4(unsigned& r0, unsigned& r1, unsigned& r2,
                                      unsigned& r3, unsigned a) {
    asm volatile("ldmatrix.sync.aligned.m8n8.x4.shared.b16 {%0,%1,%2,%3},[%4];\n"
                 : "=r"(r0), "=r"(r1), "=r"(r2), "=r"(r3) : "r"(a));
}
__device__ __forceinline__ void ldsm4t(unsigned& r0, unsigned& r1, unsigned& r2,
                                       unsigned& r3, unsigned a) {
    asm volatile("ldmatrix.sync.aligned.m8n8.x4.trans.shared.b16 {%0,%1,%2,%3},[%4];\n"
                 : "=r"(r0), "=r"(r1), "=r"(r2), "=r"(r3) : "r"(a));
}

// ---------------------------------------------------------------------------
// k_prepw: W -> bf16.
// ---------------------------------------------------------------------------
__global__ __launch_bounds__(256) void k_prepw(const float* __restrict__ W) {
    int i = blockIdx.x * 256 + threadIdx.x;
    g_wb[i] = __float2bfloat16(W[i]);
}

// ---------------------------------------------------------------------------
// k_logits: logits = W[64,512] @ x[512, 64 s] (bf16 mma). Staging: f32 LDG ->
// pack bf16 in regs -> STS (ldmatrix-friendly [k][d]/[d][s] rows) AND STG to
// g_xb (fuses the x->bf16 prep). Double-buffered, 1 bar/chunk; ldmatrix
// operand fetch. Fused: per-pixel sumsq, softmax, a_sum partial, a' -> bf16.
// grid (25, 32), 256 thr = 8 warps; warp w: k-rows [(w>>1)*16,+16),
// s-cols [(w&1)*32,+32).
// smem: W bufs [64][80B] @ 0,5120; X bufs [32][144B] @ 10240,14848.
// ---------------------------------------------------------------------------
__global__ __launch_bounds__(256) void k_logits(const float* __restrict__ x,
                                                const float* __restrict__ W) {
    const int n = blockIdx.y;
    const int s0 = blockIdx.x * 64;
    const int tid = threadIdx.x;
    const int warp = tid >> 5, lane = tid & 31;
    const int gid = lane >> 2, tig = lane & 3;
    const int k0 = (warp >> 1) * 16;
    const int sh = (warp & 1) * 32;

    __shared__ __align__(16) char sm[19456];
    const unsigned smb = (unsigned)__cvta_generic_to_shared(sm);

    const float* xb = x + (size_t)n * DDIM * SDIM + s0;
    bh* xout = g_xb + (size_t)n * DDIM * SDIM + s0;

    const int wk = tid >> 2, wc = (tid & 3) * 8;    // W: row wk, 8 d-values
    const int xd = tid >> 3, xs8 = (tid & 7) * 8;   // X: d-row xd, 8 s-values

    float acc[4][4];
#pragma unroll
    for (int j = 0; j < 4; j++)
#pragma unroll
        for (int i = 0; i < 4; i++) acc[j][i] = 0.f;
    float ss[8];
#pragma unroll
    for (int i = 0; i < 8; i++) ss[i] = 0.f;

    // ---- prologue: stage chunk 0 into buffer 0 ----
    {
        float4 w0 = *(const float4*)&W[wk * DDIM + wc];
        float4 w1 = *(const float4*)&W[wk * DDIM + wc + 4];
        uint4 wp = make_uint4(packbf(w0.x, w0.y), packbf(w0.z, w0.w),
                              packbf(w1.x, w1.y), packbf(w1.z, w1.w));
        *(uint4*)(sm + wk * 80 + wc * 2) = wp;
        const float* xr = &xb[(size_t)xd * SDIM + xs8];
        float4 x0 = *(const float4*)xr;
        float4 x1 = *(const float4*)(xr + 4);
        ss[0] += x0.x * x0.x; ss[1] += x0.y * x0.y;
        ss[2] += x0.z * x0.z; ss[3] += x0.w * x0.w;
        ss[4] += x1.x * x1.x; ss[5] += x1.y * x1.y;
        ss[6] += x1.z * x1.z; ss[7] += x1.w * x1.w;
        uint4 xp = make_uint4(packbf(x0.x, x0.y), packbf(x0.z, x0.w),
                              packbf(x1.x, x1.y), packbf(x1.z, x1.w));
        *(uint4*)(sm + 10240 + xd * 144 + xs8 * 2) = xp;
        *(uint4*)&xout[(size_t)xd * SDIM + xs8] = xp;
    }
    __syncthreads();

    const int q = lane >> 3, rr = lane & 7;
    const int offA = (k0 + (q & 1) * 8 + rr) * 80 + (q >> 1) * 16;
    const int offB = ((q & 1) * 8 + rr) * 144 + (q >> 1) * 16;

#pragma unroll 2
    for (int c = 0; c < 16; c++) {
        const int cur = (c & 1), nxt = cur ^ 1;
        const unsigned Wb = smb + cur * 5120;
        const unsigned Xb = smb + 10240 + cur * 4608;

        // prefetch next chunk to regs (overlaps mma)
        float4 nw0, nw1, nx0, nx1;
        if (c < 15) {
            const int dc = (c + 1) * 32;
            nw0 = *(const float4*)&W[wk * DDIM + dc + wc];
            nw1 = *(const float4*)&W[wk * DDIM + dc + wc + 4];
            const float* xr = &xb[(size_t)(dc + xd) * SDIM + xs8];
            nx0 = *(const float4*)xr;
            nx1 = *(const float4*)(xr + 4);
        }

#pragma unroll
        for (int kk2 = 0; kk2 < 16; kk2 += 8) {   // d-offset = 2*kk2
            unsigned a0, a1, a2, a3;
            ldsm4(a0, a1, a2, a3, Wb + offA + kk2 * 4);
#pragma unroll
            for (int np = 0; np < 2; np++) {
                unsigned b0, b1, b2, b3;
                ldsm4t(b0, b1, b2, b3,
                       Xb + offB + (kk2 * 2) * 144 + (sh + np * 16) * 2);
                mma_bf16(acc[np * 2],     a0, a1, a2, a3, b0, b1);
                mma_bf16(acc[np * 2 + 1], a0, a1, a2, a3, b2, b3);
            }
        }

        if (c < 15) {
            const int dc = (c + 1) * 32;
            ss[0] += nx0.x * nx0.x; ss[1] += nx0.y * nx0.y;
            ss[2] += nx0.z * nx0.z; ss[3] += nx0.w * nx0.w;
            ss[4] += nx1.x * nx1.x; ss[5] += nx1.y * nx1.y;
            ss[6] += nx1.z * nx1.z; ss[7] += nx1.w * nx1.w;
            uint4 wp = make_uint4(packbf(nw0.x, nw0.y), packbf(nw0.z, nw0.w),
                                  packbf(nw1.x, nw1.y), packbf(nw1.z, nw1.w));
            *(uint4*)(sm + nxt * 5120 + wk * 80 + wc * 2) = wp;
            uint4 xp = make_uint4(packbf(nx0.x, nx0.y), packbf(nx0.z, nx0.w),
                                  packbf(nx1.x, nx1.y), packbf(nx1.z, nx1.w));
            *(uint4*)(sm + 10240 + nxt * 4608 + xd * 144 + xs8 * 2) = xp;
            *(uint4*)&xout[(size_t)(dc + xd) * SDIM + xs8] = xp;
        }
        __syncthreads();
    }

    // ---- epilogue (aliases stage buffers) ----
    float (*Lsh)[65] = (float(*)[65])sm;            // 16640
    float (*ssp)[64] = (float(*)[64])(sm + 16640);  // 32x64x... reuse: per-d-row partials
    // NOTE: ssp needs 32*64*4 = 8192 > remaining; instead reduce ss in-warp
    // first: thread covers s-cols xs8..xs8+7 for d-row xd (one row/chunk).
    // Rows xd and xd+... : 8 threads per row group share the same 8 s-cols
    // across 32 different d-rows? No: row = xd fixed, so 32 row-partials per
    // s-col distributed over threads with the same (tid&7). Reduce via smem:
    float* red1   = (float*)(sm + 16640);           // 1024
    float* red2   = (float*)(sm + 17664);           // 1024
    float* sscale = (float*)(sm + 18688);           // 256
    float* sinv   = (float*)(sm + 18944);           // 256

#pragma unroll
    for (int j = 0; j < 4; j++) {
        Lsh[k0 + gid][sh + j * 8 + 2 * tig]         = acc[j][0];
        Lsh[k0 + gid][sh + j * 8 + 2 * tig + 1]     = acc[j][1];
        Lsh[k0 + gid + 8][sh + j * 8 + 2 * tig]     = acc[j][2];
        Lsh[k0 + gid + 8][sh + j * 8 + 2 * tig + 1] = acc[j][3];
    }
    // sumsq reduce: 32 threads share each s-octet (same tid&7, different xd).
    // Tree-reduce through red1/red2 in two rounds of 4.
    // Round 1: 8 groups of 4 d-rows -> red1[ (xd&7)*... ] ; simpler: atomic-free
    // two-phase via red2 as [8][64]? 8*64*4 = 2048 > 1024. Use red1+red2 (2048B)
    // as one [8][64] buffer.
    {
        float* part8 = red1;   // 2048 bytes: [8 groups][64 s]
        // phase 0: zero is avoided by having group leader write, others add via
        // shfl: threads with same xd>>2 (8 thr apart in tid? no). Do it simply:
        // warp-level: within a warp, lanes 0..31 cover xd = (warp*32+lane)>>3
        // = warp*4 + (lane>>3): 4 d-rows, 8 s-cols each. Fold across the 4
        // d-row groups within the warp via shfl by 8,16: lanes with same
        // (lane&7) combine.
        float v[8];
#pragma unroll
        for (int i = 0; i < 8; i++) v[i] = ss[i];
#pragma unroll
        for (int i = 0; i < 8; i++) {
            v[i] += __shfl_xor_sync(0xffffffffu, v[i], 8);
            v[i] += __shfl_xor_sync(0xffffffffu, v[i], 16);
        }
        // now lanes 0..7 of each warp hold sums over that warp's 4 d-rows for
        // s-cols (lane)*8? careful: s-octet is (tid&7)*8 = (lane&7)*8.
        if (lane < 8) {
            // part8[warp][ s-octet ]: warp covers d-rows warp*4..warp*4+3
#pragma unroll
            for (int i = 0; i < 8; i++)
                part8[warp * 64 + lane * 8 + i] = v[i];
        }
    }
    __syncthreads();
    // final sumsq over 8 warps + softmax. 4 threads per pixel.
    const int qq = tid >> 6, s = tid & 63;
    float tot = 0.f;
#pragma unroll
    for (int w = 0; w < 8; w++) tot += red1[w * 64 + s];   // red1+red2 region
    const float sc = 1.f / fmaxf(sqrtf(tot), 1e-12f);
    __syncthreads();   // red1/red2 about to be reused for max/sum reductions

    float m = -1e30f;
#pragma unroll
    for (int kq = 0; kq < 16; kq++) m = fmaxf(m, Lsh[qq * 16 + kq][s] * sc);
    red1[qq * 64 + s] = m;
    __syncthreads();
    m = fmaxf(fmaxf(red1[s], red1[64 + s]), fmaxf(red1[128 + s], red1[192 + s]));

    float sump = 0.f;
#pragma unroll
    for (int kq = 0; kq < 16; kq++) {
        float e = __expf(Lsh[qq * 16 + kq][s] * sc - m);
        Lsh[qq * 16 + kq][s] = e;
        sump += e;
    }
    red2[qq * 64 + s] = sump;
    if (qq == 0) sscale[s] = sc;
    __syncthreads();
    if (qq == 0) {
        float sum = red2[s] + red2[64 + s] + red2[128 + s] + red2[192 + s];
        sinv[s] = 1.f / sum;
    }
    __syncthreads();

    // a_sum partial: 4 threads per k, each sums 16 pixels
    {
        const int k = tid & 63;
        float t = 0.f;
#pragma unroll
        for (int sq = 0; sq < 16; sq++) {
            int sp = qq * 16 + sq;
            t += Lsh[k][sp] * sinv[sp];
        }
        red1[qq * 64 + k] = t;
    }
    __syncthreads();
    if (tid < 64)
        g_asum_part[((size_t)n * NTILES + blockIdx.x) * KK + tid] =
            red1[tid] + red1[64 + tid] + red1[128 + tid] + red1[192 + tid];

    // a' = softmax * invn -> bf16 pairs
    unsigned* ab32 = (unsigned*)g_a + (size_t)n * KK * (SDIM / 2) + (s0 >> 1);
#pragma unroll
    for (int i = 0; i < 8; i++) {
        int idx = tid + i * 256;
        int k = idx >> 5, s2 = (idx & 31) * 2;
        float v0 = Lsh[k][s2] * sinv[s2] * sscale[s2];
        float v1 = Lsh[k][s2 + 1] * sinv[s2 + 1] * sscale[s2 + 1];
        ab32[(size_t)k * (SDIM / 2) + (s2 >> 1)] = packbf(v0, v1);
    }
}

// ---------------------------------------------------------------------------
// k_agg: agg[d,k] += sum_s x_bf[d,s]*a'[k,s]  (bf16 mma), cp.async 3-stage
// ring + ldmatrix. grid (8 d-tiles, 32 n, 2 s-halves), 256 thr = 8 warps;
// warp w: d-rows [(w>>1)*16,+16), k-cols [(w&1)*32,+32).   [R12: 27.3us]
// smem: X stages [64][80B] @ st*5120; A stages [64][80B] @ 15360+st*5120.
// ---------------------------------------------------------------------------
__global__ __launch_bounds__(256) void k_agg() {
    const int n = blockIdx.y;
    const int d0 = blockIdx.x * 64;
    const int h = blockIdx.z;
    const int tid = threadIdx.x;
    const int warp = tid >> 5, lane = tid & 31;
    const int gid = lane >> 2, tig = lane & 3;
    const int dw0 = (warp >> 1) * 16;
    const int kh = (warp & 1) * 32;

    __shared__ __align__(16) char sm[30720];
    const unsigned smb = (unsigned)__cvta_generic_to_shared(sm);

    const bh* Xg = g_xb + ((size_t)n * DDIM + d0) * SDIM;
    const bh* Ag = g_a + (size_t)n * KK * SDIM;
    const int r = tid >> 2, ce = (tid & 3) * 8, cb = (tid & 3) * 16;
    const int sbase = h * (SDIM / 2);

#define ASTAGE(c) do {                                                        \
        int _st = (c) % 3; int _sc = sbase + (c) * 32;                        \
        cpa16(smb + _st * 5120 + r * 80 + cb,                                 \
              Xg + (size_t)r * SDIM + _sc + ce);                              \
        cpa16(smb + 15360 + _st * 5120 + r * 80 + cb,                         \
              Ag + (size_t)r * SDIM + _sc + ce);                              \
        cp_commit(); } while (0)

    float acc[4][4];
#pragma unroll
    for (int j = 0; j < 4; j++)
#pragma unroll
        for (int i = 0; i < 4; i++) acc[j][i] = 0.f;

    ASTAGE(0);
    ASTAGE(1);

    const int q = lane >> 3, rr = lane & 7;
    const int offA = (dw0 + (q & 1) * 8 + rr) * 80 + (q >> 1) * 16;
    const int offB = (kh + q * 8 + rr) * 80;

    for (int c = 0; c < 25; c++) {
        if (c < 24) cp_wait<1>(); else cp_wait<0>();
        __syncthreads();
        const unsigned Xb = smb + (c % 3) * 5120;
        const unsigned Ab = smb + 15360 + (c % 3) * 5120;
#pragma unroll
        for (int kk2 = 0; kk2 < 16; kk2 += 8) {
            unsigned a0, a1, a2, a3;
            ldsm4(a0, a1, a2, a3, Xb + offA + kk2 * 4);
            unsigned p0, p1, p2, p3, q0, q1, q2, q3;
            ldsm4(p0, p1, p2, p3, Ab + offB + kk2 * 4);
            ldsm4(q0, q1, q2, q3, Ab + offB + kk2 * 4 + 16);
            mma_bf16(acc[0], a0, a1, a2, a3, p0, q0);
            mma_bf16(acc[1], a0, a1, a2, a3, p1, q1);
            mma_bf16(acc[2], a0, a1, a2, a3, p2, q2);
            mma_bf16(acc[3], a0, a1, a2, a3, p3, q3);
        }
        if (c + 2 < 25) ASTAGE(c + 2);
        else cp_commit();
    }
    __syncthreads();
#undef ASTAGE

    float (*Tsh)[68] = (float(*)[68])sm;   // aliases stages
#pragma unroll
    for (int j = 0; j < 4; j++) {
        Tsh[kh + j * 8 + 2 * tig][dw0 + gid]         = acc[j][0];
        Tsh[kh + j * 8 + 2 * tig + 1][dw0 + gid]     = acc[j][1];
        Tsh[kh + j * 8 + 2 * tig][dw0 + gid + 8]     = acc[j][2];
        Tsh[kh + j * 8 + 2 * tig + 1][dw0 + gid + 8] = acc[j][3];
    }
    __syncthreads();
    float* dst = &g_agg2[h][(size_t)n * KK * DDIM + d0];
#pragma unroll
    for (int i = 0; i < 4; i++) {
        int idx = tid + i * 256;
        int k = idx >> 4, dd4 = (idx & 15) * 4;
        *(float4*)&dst[(size_t)k * DDIM + dd4] = *(const float4*)&Tsh[k][dd4];
    }
}

// ---------------------------------------------------------------------------
// k_final: a_sum reduce; vlad = (agg0+agg1) - a_sum*c; intra-norm; *1/8.
// grid (64,32), 128 thr.
// ---------------------------------------------------------------------------
__global__ __launch_bounds__(128) void k_final(const float* __restrict__ cent,
                                               float* __restrict__ out) {
    const int k = blockIdx.x, n = blockIdx.y;
    const int tid = threadIdx.x;

    __shared__ float s_as;
    __shared__ float wpart[4];

    if (tid < 32) {
        float p = (tid < NTILES)
                      ? g_asum_part[((size_t)n * NTILES + tid) * KK + k]
                      : 0.f;
#pragma unroll
        for (int o = 16; o > 0; o >>= 1) p += __shfl_xor_sync(0xffffffffu, p, o);
        if (tid == 0) s_as = p;
    }
    __syncthreads();
    const float as = s_as;

    const size_t base = ((size_t)n * KK + k) * DDIM + tid * 4;
    float4 a0 = *(const float4*)&g_agg2[0][base];
    float4 a1 = *(const float4*)&g_agg2[1][base];
    float4 c4 = *(const float4*)&cent[(size_t)k * DDIM + tid * 4];
    float vx = a0.x + a1.x - as * c4.x;
    float vy = a0.y + a1.y - as * c4.y;
    float vz = a0.z + a1.z - as * c4.z;
    float vw = a0.w + a1.w - as * c4.w;
    float ss = vx * vx + vy * vy + vz * vz + vw * vw;

#pragma unroll
    for (int o = 16; o > 0; o >>= 1) ss += __shfl_xor_sync(0xffffffffu, ss, o);
    if ((tid & 31) == 0) wpart[tid >> 5] = ss;
    __syncthreads();
    float tot = wpart[0] + wpart[1] + wpart[2] + wpart[3];

    const float inv = 0.125f / fmaxf(sqrtf(tot), 1e-12f);
    float4 o4 = make_float4(vx * inv, vy * inv, vz * inv, vw * inv);
    *(float4*)&out[(size_t)n * (KK * DDIM) + (size_t)k * DDIM + tid * 4] = o4;
}

extern "C" void kernel_launch(void* const* d_in, const int* in_sizes, int n_in,
                              void* d_out, int out_size) {
    const float* x    = (const float*)d_in[0];
    const float* W    = (const float*)d_in[1];
    const float* cent = (const float*)d_in[2];
    float* out = (float*)d_out;

    k_prepw<<<128, 256>>>(W);
    k_logits<<<dim3(NTILES, NN), 256>>>(x, W);
    k_agg<<<dim3(8, NN, 2), 256>>>();
    k_final<<<dim3(KK, NN), 128>>>(cent, out);
}

// round 16
// speedup vs baseline: 1.2635x; 1.0034x over previous
#include <cuda_runtime.h>
#include <cuda_bf16.h>
#include <math.h>

// NetVLAD: N=32, D=512, S=1600, K=64.
// d_in[0]=x [N,D,S] f32, d_in[1]=W [K,D] f32, d_in[2]=centroids [K,D] f32
// out: [N, K*D] f32

#define NN 32
#define DDIM 512
#define SDIM 1600
#define KK 64
#define NTILES 25   // s-tiles of 64

typedef __nv_bfloat16 bh;

__device__ __align__(16) bh g_xb[NN * DDIM * SDIM + 512]; // x bf16 (+tail pad)
__device__ __align__(16) bh g_wb[KK * DDIM];              // W bf16
__device__ __align__(16) bh g_a[NN * KK * SDIM + 512];    // a' (+tail pad)
__device__ __align__(16) float g_agg4[4][NN * KK * DDIM]; // agg, 4 s-quarters
__device__ __align__(16) float g_asum_part[NN * NTILES * KK];

__device__ __forceinline__ unsigned packbf(float lo, float hi) {
    __nv_bfloat162 h = __floats2bfloat162_rn(lo, hi);
    return *(unsigned*)&h;
}

__device__ __forceinline__ void mma_bf16(float* c, unsigned a0, unsigned a1,
                                         unsigned a2, unsigned a3,
                                         unsigned b0, unsigned b1) {
    asm volatile(
        "mma.sync.aligned.m16n8k16.row.col.f32.bf16.bf16.f32 "
        "{%0,%1,%2,%3},{%4,%5,%6,%7},{%8,%9},{%0,%1,%2,%3};\n"
        : "+f"(c[0]), "+f"(c[1]), "+f"(c[2]), "+f"(c[3])
        : "r"(a0), "r"(a1), "r"(a2), "r"(a3), "r"(b0), "r"(b1));
}

__device__ __forceinline__ void cpa16(unsigned dst, const void* src) {
    asm volatile("cp.async.ca.shared.global [%0], [%1], 16;\n"
                 :: "r"(dst), "l"(src));
}
// zero-fill variant: copies sz bytes (0 or 16), zero-fills the rest of 16.
__device__ __forceinline__ void cpa16z(unsigned dst, const void* src, int sz) {
    asm volatile("cp.async.ca.shared.global [%0], [%1], 16, %2;\n"
                 :: "r"(dst), "l"(src), "r"(sz));
}
__device__ __forceinline__ void cp_commit() {
    asm volatile("cp.async.commit_group;\n");
}
template <int N> __device__ __forceinline__ void cp_wait() {
    asm volatile("cp.async.wait_group %0;\n" :: "n"(N));
}
__device__ __forceinline__ void ldsm4(unsigned& r0, unsigned& r1, unsigned& r2,
                                      unsigned& r3, unsigned a) {
    asm volatile("ldmatrix.sync.aligned.m8n8.x4.shared.b16 {%0,%1,%2,%3},[%4];\n"
                 : "=r"(r0), "=r"(r1), "=r"(r2), "=r"(r3) : "r"(a));
}
__device__ __forceinline__ void ldsm4t(unsigned& r0, unsigned& r1, unsigned& r2,
                                       unsigned& r3, unsigned a) {
    asm volatile("ldmatrix.sync.aligned.m8n8.x4.trans.shared.b16 {%0,%1,%2,%3},[%4];\n"
                 : "=r"(r0), "=r"(r1), "=r"(r2), "=r"(r3) : "r"(a));
}

// ---------------------------------------------------------------------------
// k_prepw: W -> bf16.
// ---------------------------------------------------------------------------
__global__ __launch_bounds__(256) void k_prepw(const float* __restrict__ W) {
    int i = blockIdx.x * 256 + threadIdx.x;
    g_wb[i] = __float2bfloat16(W[i]);
}

// ---------------------------------------------------------------------------
// k_logits: logits = W[64,512] @ x[512, 64 s] (bf16 mma). W staged via
// cp.async from g_wb (bf16); x staged f32 LDG -> pack -> STS + STG to g_xb
// (fused x->bf16 prep). Double-buffered, 1 bar/chunk; ldmatrix operands.
// Fused: per-pixel sumsq, softmax, a_sum partial, a' -> bf16.
// grid (25, 32), 256 thr = 8 warps; warp w: k-rows [(w>>1)*16,+16),
// s-cols [(w&1)*32,+32).
// smem: W bufs [64][80B] @ 0,5120; X bufs [32][144B] @ 10240,14848.
// ---------------------------------------------------------------------------
__global__ __launch_bounds__(256) void k_logits(const float* __restrict__ x) {
    const int n = blockIdx.y;
    const int s0 = blockIdx.x * 64;
    const int tid = threadIdx.x;
    const int warp = tid >> 5, lane = tid & 31;
    const int gid = lane >> 2, tig = lane & 3;
    const int k0 = (warp >> 1) * 16;
    const int sh = (warp & 1) * 32;

    __shared__ __align__(16) char sm[19456];
    const unsigned smb = (unsigned)__cvta_generic_to_shared(sm);

    const float* xb = x + (size_t)n * DDIM * SDIM + s0;
    bh* xout = g_xb + (size_t)n * DDIM * SDIM + s0;

    const int wk = tid >> 2, wc = (tid & 3) * 8;    // W: row wk, 8 bf16
    const int xd = tid >> 3, xs8 = (tid & 7) * 8;   // X: d-row xd, 8 s

    float acc[4][4];
#pragma unroll
    for (int j = 0; j < 4; j++)
#pragma unroll
        for (int i = 0; i < 4; i++) acc[j][i] = 0.f;
    float ss[8];
#pragma unroll
    for (int i = 0; i < 8; i++) ss[i] = 0.f;

    // ---- prologue: stage chunk 0 into buffer 0 ----
    cpa16(smb + wk * 80 + (tid & 3) * 16, g_wb + wk * DDIM + wc);
    cp_commit();
    {
        const float* xr = &xb[(size_t)xd * SDIM + xs8];
        float4 x0 = *(const float4*)xr;
        float4 x1 = *(const float4*)(xr + 4);
        ss[0] += x0.x * x0.x; ss[1] += x0.y * x0.y;
        ss[2] += x0.z * x0.z; ss[3] += x0.w * x0.w;
        ss[4] += x1.x * x1.x; ss[5] += x1.y * x1.y;
        ss[6] += x1.z * x1.z; ss[7] += x1.w * x1.w;
        uint4 xp = make_uint4(packbf(x0.x, x0.y), packbf(x0.z, x0.w),
                              packbf(x1.x, x1.y), packbf(x1.z, x1.w));
        *(uint4*)(sm + 10240 + xd * 144 + xs8 * 2) = xp;
        *(uint4*)&xout[(size_t)xd * SDIM + xs8] = xp;
    }
    cp_wait<0>();
    __syncthreads();

    const int q = lane >> 3, rr = lane & 7;
    const int offA = (k0 + (q & 1) * 8 + rr) * 80 + (q >> 1) * 16;
    const int offB = ((q & 1) * 8 + rr) * 144 + (q >> 1) * 16;

#pragma unroll 2
    for (int c = 0; c < 16; c++) {
        const int cur = (c & 1), nxt = cur ^ 1;
        const unsigned Wb = smb + cur * 5120;
        const unsigned Xb = smb + 10240 + cur * 4608;

        // issue next W cp.async + x LDG before compute (overlap with mma)
        float4 nx0, nx1;
        if (c < 15) {
            const int dc = (c + 1) * 32;
            cpa16(smb + nxt * 5120 + wk * 80 + (tid & 3) * 16,
                  g_wb + wk * DDIM + dc + wc);
            cp_commit();
            const float* xr = &xb[(size_t)(dc + xd) * SDIM + xs8];
            nx0 = *(const float4*)xr;
            nx1 = *(const float4*)(xr + 4);
        }

#pragma unroll
        for (int kk2 = 0; kk2 < 16; kk2 += 8) {   // d-offset = 2*kk2
            unsigned a0, a1, a2, a3;
            ldsm4(a0, a1, a2, a3, Wb + offA + kk2 * 4);
#pragma unroll
            for (int np = 0; np < 2; np++) {
                unsigned b0, b1, b2, b3;
                ldsm4t(b0, b1, b2, b3,
                       Xb + offB + (kk2 * 2) * 144 + (sh + np * 16) * 2);
                mma_bf16(acc[np * 2],     a0, a1, a2, a3, b0, b1);
                mma_bf16(acc[np * 2 + 1], a0, a1, a2, a3, b2, b3);
            }
        }

        if (c < 15) {
            const int dc = (c + 1) * 32;
            ss[0] += nx0.x * nx0.x; ss[1] += nx0.y * nx0.y;
            ss[2] += nx0.z * nx0.z; ss[3] += nx0.w * nx0.w;
            ss[4] += nx1.x * nx1.x; ss[5] += nx1.y * nx1.y;
            ss[6] += nx1.z * nx1.z; ss[7] += nx1.w * nx1.w;
            uint4 xp = make_uint4(packbf(nx0.x, nx0.y), packbf(nx0.z, nx0.w),
                                  packbf(nx1.x, nx1.y), packbf(nx1.z, nx1.w));
            *(uint4*)(sm + 10240 + nxt * 4608 + xd * 144 + xs8 * 2) = xp;
            *(uint4*)&xout[(size_t)(dc + xd) * SDIM + xs8] = xp;
        }
        cp_wait<0>();
        __syncthreads();
    }

    // ---- epilogue (aliases stage buffers) ----
    float (*Lsh)[65] = (float(*)[65])sm;            // 16640
    float* red1   = (float*)(sm + 16640);           // 1024 (with red2: [8][64])
    float* red2   = (float*)(sm + 17664);           // 1024
    float* sscale = (float*)(sm + 18688);           // 256
    float* sinv   = (float*)(sm + 18944);           // 256

#pragma unroll
    for (int j = 0; j < 4; j++) {
        Lsh[k0 + gid][sh + j * 8 + 2 * tig]         = acc[j][0];
        Lsh[k0 + gid][sh + j * 8 + 2 * tig + 1]     = acc[j][1];
        Lsh[k0 + gid + 8][sh + j * 8 + 2 * tig]     = acc[j][2];
        Lsh[k0 + gid + 8][sh + j * 8 + 2 * tig + 1] = acc[j][3];
    }
    // sumsq: fold 4 d-row groups within each warp (lanes with same lane&7),
    // then one [8 warps][64 s] partial buffer in red1/red2.
    {
        float v[8];
#pragma unroll
        for (int i = 0; i < 8; i++) v[i] = ss[i];
#pragma unroll
        for (int i = 0; i < 8; i++) {
            v[i] += __shfl_xor_sync(0xffffffffu, v[i], 8);
            v[i] += __shfl_xor_sync(0xffffffffu, v[i], 16);
        }
        if (lane < 8) {
#pragma unroll
            for (int i = 0; i < 8; i++)
                red1[warp * 64 + lane * 8 + i] = v[i];
        }
    }
    __syncthreads();
    const int qq = tid >> 6, s = tid & 63;
    float tot = 0.f;
#pragma unroll
    for (int w = 0; w < 8; w++) tot += red1[w * 64 + s];
    const float sc = 1.f / fmaxf(sqrtf(tot), 1e-12f);
    __syncthreads();

    float m = -1e30f;
#pragma unroll
    for (int kq = 0; kq < 16; kq++) m = fmaxf(m, Lsh[qq * 16 + kq][s] * sc);
    red1[qq * 64 + s] = m;
    __syncthreads();
    m = fmaxf(fmaxf(red1[s], red1[64 + s]), fmaxf(red1[128 + s], red1[192 + s]));

    float sump = 0.f;
#pragma unroll
    for (int kq = 0; kq < 16; kq++) {
        float e = __expf(Lsh[qq * 16 + kq][s] * sc - m);
        Lsh[qq * 16 + kq][s] = e;
        sump += e;
    }
    red2[qq * 64 + s] = sump;
    if (qq == 0) sscale[s] = sc;
    __syncthreads();
    if (qq == 0) {
        float sum = red2[s] + red2[64 + s] + red2[128 + s] + red2[192 + s];
        sinv[s] = 1.f / sum;
    }
    __syncthreads();

    {
        const int k = tid & 63;
        float t = 0.f;
#pragma unroll
        for (int sq = 0; sq < 16; sq++) {
            int sp = qq * 16 + sq;
            t += Lsh[k][sp] * sinv[sp];
        }
        red1[qq * 64 + k] = t;
    }
    __syncthreads();
    if (tid < 64)
        g_asum_part[((size_t)n * NTILES + blockIdx.x) * KK + tid] =
            red1[tid] + red1[64 + tid] + red1[128 + tid] + red1[192 + tid];

    unsigned* ab32 = (unsigned*)g_a + (size_t)n * KK * (SDIM / 2) + (s0 >> 1);
#pragma unroll
    for (int i = 0; i < 8; i++) {
        int idx = tid + i * 256;
        int k = idx >> 5, s2 = (idx & 31) * 2;
        float v0 = Lsh[k][s2] * sinv[s2] * sscale[s2];
        float v1 = Lsh[k][s2 + 1] * sinv[s2 + 1] * sscale[s2 + 1];
        ab32[(size_t)k * (SDIM / 2) + (s2 >> 1)] = packbf(v0, v1);
    }
}

// ---------------------------------------------------------------------------
// k_agg: agg[d,k] += sum_s x_bf[d,s]*a'[k,s]  (bf16 mma), cp.async 3-stage
// ring + ldmatrix. grid (8 d-tiles, 32 n, 4 s-quarters) = 1024 CTAs
// (6.9/SM), 256 thr = 8 warps; warp w: d-rows [(w>>1)*16,+16), k-cols
// [(w&1)*32,+32). 400 s = 13 chunks of 32; tail zero-filled on a' (x*0=0).
// smem: X stages [64][80B] @ st*5120; A stages [64][80B] @ 15360+st*5120.
// ---------------------------------------------------------------------------
__global__ __launch_bounds__(256) void k_agg() {
    const int n = blockIdx.y;
    const int d0 = blockIdx.x * 64;
    const int h = blockIdx.z;          // s-quarter
    const int tid = threadIdx.x;
    const int warp = tid >> 5, lane = tid & 31;
    const int gid = lane >> 2, tig = lane & 3;
    const int dw0 = (warp >> 1) * 16;
    const int kh = (warp & 1) * 32;

    __shared__ __align__(16) char sm[30720];
    const unsigned smb = (unsigned)__cvta_generic_to_shared(sm);

    const bh* Xg = g_xb + ((size_t)n * DDIM + d0) * SDIM;
    const bh* Ag = g_a + (size_t)n * KK * SDIM;
    const int r = tid >> 2, ce = (tid & 3) * 8, cb = (tid & 3) * 16;
    const int sbase = h * 400;

#define ASTAGE(c) do {                                                        \
        int _st = (c) % 3; int _sc = sbase + (c) * 32;                        \
        int _sz = ((c) * 32 + ce < 400) ? 16 : 0;                             \
        cpa16(smb + _st * 5120 + r * 80 + cb,                                 \
              Xg + (size_t)r * SDIM + _sc + ce);                              \
        cpa16z(smb + 15360 + _st * 5120 + r * 80 + cb,                        \
               Ag + (size_t)r * SDIM + _sc + ce, _sz);                        \
        cp_commit(); } while (0)

    float acc[4][4];
#pragma unroll
    for (int j = 0; j < 4; j++)
#pragma unroll
        for (int i = 0; i < 4; i++) acc[j][i] = 0.f;

    ASTAGE(0);
    ASTAGE(1);

    const int q = lane >> 3, rr = lane & 7;
    const int offA = (dw0 + (q & 1) * 8 + rr) * 80 + (q >> 1) * 16;
    const int offB = (kh + q * 8 + rr) * 80;

    for (int c = 0; c < 13; c++) {
        if (c < 12) cp_wait<1>(); else cp_wait<0>();
        __syncthreads();
        const unsigned Xb = smb + (c % 3) * 5120;
        const unsigned Ab = smb + 15360 + (c % 3) * 5120;
#pragma unroll
        for (int kk2 = 0; kk2 < 16; kk2 += 8) {
            unsigned a0, a1, a2, a3;
            ldsm4(a0, a1, a2, a3, Xb + offA + kk2 * 4);
            unsigned p0, p1, p2, p3, q0, q1, q2, q3;
            ldsm4(p0, p1, p2, p3, Ab + offB + kk2 * 4);
            ldsm4(q0, q1, q2, q3, Ab + offB + kk2 * 4 + 16);
            mma_bf16(acc[0], a0, a1, a2, a3, p0, q0);
            mma_bf16(acc[1], a0, a1, a2, a3, p1, q1);
            mma_bf16(acc[2], a0, a1, a2, a3, p2, q2);
            mma_bf16(acc[3], a0, a1, a2, a3, p3, q3);
        }
        if (c + 2 < 13) ASTAGE(c + 2);
        else cp_commit();
    }
    __syncthreads();
#undef ASTAGE

    float (*Tsh)[68] = (float(*)[68])sm;   // aliases stages
#pragma unroll
    for (int j = 0; j < 4; j++) {
        Tsh[kh + j * 8 + 2 * tig][dw0 + gid]         = acc[j][0];
        Tsh[kh + j * 8 + 2 * tig + 1][dw0 + gid]     = acc[j][1];
        Tsh[kh + j * 8 + 2 * tig][dw0 + gid + 8]     = acc[j][2];
        Tsh[kh + j * 8 + 2 * tig + 1][dw0 + gid + 8] = acc[j][3];
    }
    __syncthreads();
    float* dst = &g_agg4[h][(size_t)n * KK * DDIM + d0];
#pragma unroll
    for (int i = 0; i < 4; i++) {
        int idx = tid + i * 256;
        int k = idx >> 4, dd4 = (idx & 15) * 4;
        *(float4*)&dst[(size_t)k * DDIM + dd4] = *(const float4*)&Tsh[k][dd4];
    }
}

// ---------------------------------------------------------------------------
// k_final: a_sum reduce; vlad = sum(agg quarters) - a_sum*c; intra-norm; *1/8
// (global norm of 64 unit rows is exactly 8). grid (64,32), 128 thr.
// ---------------------------------------------------------------------------
__global__ __launch_bounds__(128) void k_final(const float* __restrict__ cent,
                                               float* __restrict__ out) {
    const int k = blockIdx.x, n = blockIdx.y;
    const int tid = threadIdx.x;

    __shared__ float s_as;
    __shared__ float wpart[4];

    if (tid < 32) {
        float p = (tid < NTILES)
                      ? g_asum_part[((size_t)n * NTILES + tid) * KK + k]
                      : 0.f;
#pragma unroll
        for (int o = 16; o > 0; o >>= 1) p += __shfl_xor_sync(0xffffffffu, p, o);
        if (tid == 0) s_as = p;
    }
    __syncthreads();
    const float as = s_as;

    const size_t base = ((size_t)n * KK + k) * DDIM + tid * 4;
    float4 a0 = *(const float4*)&g_agg4[0][base];
    float4 a1 = *(const float4*)&g_agg4[1][base];
    float4 a2 = *(const float4*)&g_agg4[2][base];
    float4 a3 = *(const float4*)&g_agg4[3][base];
    float4 c4 = *(const float4*)&cent[(size_t)k * DDIM + tid * 4];
    float vx = (a0.x + a1.x) + (a2.x + a3.x) - as * c4.x;
    float vy = (a0.y + a1.y) + (a2.y + a3.y) - as * c4.y;
    float vz = (a0.z + a1.z) + (a2.z + a3.z) - as * c4.z;
    float vw = (a0.w + a1.w) + (a2.w + a3.w) - as * c4.w;
    float ss = vx * vx + vy * vy + vz * vz + vw * vw;

#pragma unroll
    for (int o = 16; o > 0; o >>= 1) ss += __shfl_xor_sync(0xffffffffu, ss, o);
    if ((tid & 31) == 0) wpart[tid >> 5] = ss;
    __syncthreads();
    float tot = wpart[0] + wpart[1] + wpart[2] + wpart[3];

    const float inv = 0.125f / fmaxf(sqrtf(tot), 1e-12f);
    float4 o4 = make_float4(vx * inv, vy * inv, vz * inv, vw * inv);
    *(float4*)&out[(size_t)n * (KK * DDIM) + (size_t)k * DDIM + tid * 4] = o4;
}

extern "C" void kernel_launch(void* const* d_in, const int* in_sizes, int n_in,
                              void* d_out, int out_size) {
    const float* x    = (const float*)d_in[0];
    const float* W    = (const float*)d_in[1];
    const float* cent = (const float*)d_in[2];
    float* out = (float*)d_out;

    k_prepw<<<128, 256>>>(W);
    k_logits<<<dim3(NTILES, NN), 256>>>(x);
    k_agg<<<dim3(8, NN, 4), 256>>>();
    k_final<<<dim3(KK, NN), 128>>>(cent, out);
}